// round 2
// baseline (speedup 1.0000x reference)
#include <cuda_runtime.h>
#include <math.h>

// Problem constants
#define T_DIM   1024
#define B_DIM   8
#define INDIM   512
#define NOUT    192          // 64 v + 64 k + 64 alpha
#define M_TOT   (T_DIM*B_DIM)   // 8192 rows (t,b)
#define NCH     32           // chunks for log-cumsum (chunk = 32 t)
#define NSEG    4            // segments for the S scan (seg = 256 t)
#define SEGT    256

// ---------------- device scratch (no allocations allowed) ----------------
__device__ float  g_Wt[INDIM*NOUT];     // transposed+concatenated weights [k][n]
__device__ float  g_bias[NOUT];
__device__ float  g_v [M_TOT*64];       // v   (index m*64+d, m = t*8+b)
__device__ float  g_k [M_TOT*64];       // k
__device__ float  g_la[M_TOT*64];       // log(max(sigmoid(a),eps))  (fp32, like reference)
__device__ float  g_kd[M_TOT*64];       // k * decay
__device__ double g_csumd[NCH*512];     // per-chunk log sums (double)
__device__ float  g_P[(NSEG-1)*B_DIM*64*64];  // segment partial outer sums

// ---------------- K0: pack weights (transpose to [k][n]) + bias ----------------
__global__ void pack_weights(const float* __restrict__ Wv, const float* __restrict__ bv,
                             const float* __restrict__ Wk, const float* __restrict__ bk,
                             const float* __restrict__ Wa, const float* __restrict__ ba){
    int idx = blockIdx.x*256 + threadIdx.x;
    if (idx < NOUT*INDIM){
        int j = idx / INDIM;          // output col 0..191
        int k = idx - j*INDIM;        // k 0..511 (coalesced read)
        const float* W = (j < 64) ? Wv : ((j < 128) ? Wk : Wa);
        g_Wt[k*NOUT + j] = W[(j & 63)*INDIM + k];
    }
    if (idx < NOUT){
        g_bias[idx] = (idx < 64) ? bv[idx] : ((idx < 128) ? bk[idx-64] : ba[idx-128]);
    }
}

// ---------------- K1: projection GEMM (8192 x 512) x (512 x 192) ----------------
// Block: 256 threads; tile 64 rows x 192 cols. Thread: 4 rows x 12 cols, plain fmaf.
__global__ void __launch_bounds__(256) proj_kernel(const float* __restrict__ x){
    __shared__ float sW[16*192];   // 12 KB  (k-tile x all 192 n)
    __shared__ float sX[16*64];    // 4 KB   (k-tile x 64 m, transposed)
    __shared__ float sB[192];

    int tid = threadIdx.x;
    int tx = tid & 15;             // n-group: 12 cols
    int ty = tid >> 4;             // m-group: 4 rows (0..15)
    if (tid < 192) sB[tid] = g_bias[tid];
    int mb = blockIdx.x * 64;

    float acc[4][12];
    #pragma unroll
    for (int i = 0; i < 4; i++)
        #pragma unroll
        for (int j = 0; j < 12; j++) acc[i][j] = 0.0f;

    for (int kk = 0; kk < INDIM; kk += 16){
        // W tile: 16*192 = 3072 floats = 768 float4 (3 per thread)
        {
            const float4* src = (const float4*)&g_Wt[kk*NOUT];
            float4* dst = (float4*)sW;
            dst[tid]       = src[tid];
            dst[tid + 256] = src[tid + 256];
            dst[tid + 512] = src[tid + 512];
        }
        // X tile, transposed: sX[k][m]; m = tid>>2 (0..63), kq = tid&3
        {
            int m  = tid >> 2;
            int kq = tid & 3;
            float4 xv = *(const float4*)&x[(mb + m)*INDIM + kk + kq*4];
            sX[(kq*4+0)*64 + m] = xv.x;
            sX[(kq*4+1)*64 + m] = xv.y;
            sX[(kq*4+2)*64 + m] = xv.z;
            sX[(kq*4+3)*64 + m] = xv.w;
        }
        __syncthreads();
        #pragma unroll
        for (int k = 0; k < 16; k++){
            float4 xr = *(float4*)&sX[k*64 + ty*4];
            float xm[4] = {xr.x, xr.y, xr.z, xr.w};
            float4 w0 = *(float4*)&sW[k*192 + tx*12 + 0];
            float4 w1 = *(float4*)&sW[k*192 + tx*12 + 4];
            float4 w2 = *(float4*)&sW[k*192 + tx*12 + 8];
            float wv[12] = {w0.x,w0.y,w0.z,w0.w, w1.x,w1.y,w1.z,w1.w, w2.x,w2.y,w2.z,w2.w};
            #pragma unroll
            for (int mi = 0; mi < 4; mi++)
                #pragma unroll
                for (int nj = 0; nj < 12; nj++)
                    acc[mi][nj] = fmaf(xm[mi], wv[nj], acc[mi][nj]);
        }
        __syncthreads();
    }

    // epilogue: bias + routing (v / k / log-sigmoid alpha in double)
    #pragma unroll
    for (int mi = 0; mi < 4; mi++){
        int m = mb + ty*4 + mi;      // = t*8 + b
        #pragma unroll
        for (int nj = 0; nj < 12; nj++){
            int n = tx*12 + nj;
            float val = acc[mi][nj] + sB[n];
            if (n < 64){
                g_v[m*64 + n] = val;
            } else if (n < 128){
                g_k[m*64 + (n - 64)] = val;
            } else {
                double sg = 1.0 / (1.0 + exp(-(double)val));
                double sgc = fmax(sg, (double)1e-8f);
                g_la[m*64 + (n - 128)] = (float)log(sgc);
            }
        }
    }
}

// ---------------- K2a: per-chunk log sums (double) ----------------
__global__ void __launch_bounds__(512) chunk_logsum(){
    int c  = blockIdx.x;           // chunk 0..31
    int bn = threadIdx.x;          // (b*64+n) 0..511
    const float* p = g_la + c*32*512 + bn;
    double s = 0.0;
    #pragma unroll
    for (int i = 0; i < 32; i++) s += (double)p[i*512];
    g_csumd[c*512 + bn] = s;
}

// ---------------- K2b: decay (double) + fold into k ----------------
__global__ void __launch_bounds__(512) decay_fold(){
    int c  = blockIdx.x;
    int bn = threadIdx.x;
    double carry = 0.0, total = 0.0;
    #pragma unroll
    for (int j = 0; j < NCH; j++){
        double cs = g_csumd[j*512 + bn];
        if (j < c) carry += cs;
        total += cs;
    }
    double denom = exp(total) + (double)1e-8f;   // matches ref: fp32 cumprod[-1] underflows to 0
    double cum = carry;
    const float* lap = g_la + c*32*512 + bn;
    const float* kp  = g_k  + c*32*512 + bn;
    float*       kdp = g_kd + c*32*512 + bn;
    #pragma unroll
    for (int i = 0; i < 32; i++){
        cum += (double)lap[i*512];
        float dec = (float)(exp(cum) / denom);
        kdp[i*512] = kp[i*512] * dec;
    }
}

// ---------------- K4: segment partial outer sums ----------------
// grid (16 dq, 8 b, NSEG-1 seg), block 64 = (dg 0..3) x (nq 0..15)
__global__ void __launch_bounds__(64) seg_partial(){
    int dq = blockIdx.x, b = blockIdx.y, seg = blockIdx.z;
    __shared__ float s_v[SEGT*4];
    int tid = threadIdx.x;
    for (int i = tid; i < SEGT; i += 64){
        float4 vv = *(const float4*)&g_v[(seg*SEGT + i)*512 + b*64 + dq*4];
        *(float4*)&s_v[i*4] = vv;
    }
    __syncthreads();
    int dg = tid >> 4, nq = tid & 15;
    int d = dq*4 + dg;
    float4 acc = make_float4(0.f, 0.f, 0.f, 0.f);
    const float* kdp = g_kd + seg*SEGT*512 + b*64 + nq*4;
    #pragma unroll 8
    for (int t = 0; t < SEGT; t++){
        float4 kd = *(const float4*)(kdp + t*512);
        float vv = s_v[t*4 + dg];
        acc.x = fmaf(vv, kd.x, acc.x);
        acc.y = fmaf(vv, kd.y, acc.y);
        acc.z = fmaf(vv, kd.z, acc.z);
        acc.w = fmaf(vv, kd.w, acc.w);
    }
    *(float4*)&g_P[(seg*B_DIM + b)*4096 + d*64 + nq*4] = acc;
}

// ---------------- K5: segmented scan + store (128 MB) ----------------
// grid (16 dq, 8 b, NSEG seg), block 64 = (dg 0..3) x (nq 0..15)
__global__ void __launch_bounds__(64) scan_kernel(float* __restrict__ out){
    int dq = blockIdx.x, b = blockIdx.y, seg = blockIdx.z;
    __shared__ float s_v[SEGT*4];
    int tid = threadIdx.x;
    for (int i = tid; i < SEGT; i += 64){
        float4 vv = *(const float4*)&g_v[(seg*SEGT + i)*512 + b*64 + dq*4];
        *(float4*)&s_v[i*4] = vv;
    }
    __syncthreads();
    int dg = tid >> 4, nq = tid & 15;
    int d = dq*4 + dg;
    float4 acc = make_float4(0.f, 0.f, 0.f, 0.f);
    for (int s = 0; s < seg; s++){
        float4 pv = *(const float4*)&g_P[(s*B_DIM + b)*4096 + d*64 + nq*4];
        acc.x += pv.x; acc.y += pv.y; acc.z += pv.z; acc.w += pv.w;
    }
    const float* kdp = g_kd + seg*SEGT*512 + b*64 + nq*4;
    float* outp = out + (size_t)(seg*SEGT)*32768 + b*4096 + d*64 + nq*4;
    #pragma unroll 8
    for (int t = 0; t < SEGT; t++){
        float4 kd = *(const float4*)(kdp + t*512);
        float vv = s_v[t*4 + dg];
        acc.x = fmaf(vv, kd.x, acc.x);
        acc.y = fmaf(vv, kd.y, acc.y);
        acc.z = fmaf(vv, kd.z, acc.z);
        acc.w = fmaf(vv, kd.w, acc.w);
        *(float4*)(outp + (size_t)t*32768) = acc;
    }
}

// ---------------- launch ----------------
extern "C" void kernel_launch(void* const* d_in, const int* in_sizes, int n_in,
                              void* d_out, int out_size){
    const float* x  = (const float*)d_in[0];
    const float* Wv = (const float*)d_in[1];
    const float* bv = (const float*)d_in[2];
    const float* Wk = (const float*)d_in[3];
    const float* bk = (const float*)d_in[4];
    const float* Wa = (const float*)d_in[5];
    const float* ba = (const float*)d_in[6];
    float* out = (float*)d_out;

    pack_weights<<<(NOUT*INDIM + 255)/256, 256>>>(Wv, bv, Wk, bk, Wa, ba);
    proj_kernel<<<M_TOT/64, 256>>>(x);
    chunk_logsum<<<NCH, 512>>>();
    decay_fold<<<NCH, 512>>>();
    dim3 g4(16, B_DIM, NSEG-1);
    seg_partial<<<g4, 64>>>();
    dim3 g5(16, B_DIM, NSEG);
    scan_kernel<<<g5, 64>>>(out);
}

// round 3
// speedup vs baseline: 4.0372x; 4.0372x over previous
#include <cuda_runtime.h>
#include <math.h>

// Problem constants
#define T_DIM   1024
#define B_DIM   8
#define INDIM   512
#define NOUT    192          // 64 v + 64 k + 64 alpha
#define M_TOT   (T_DIM*B_DIM)   // 8192 rows (t,b)
#define NCH     128          // chunks for log-cumsum (chunk = 8 t)
#define TCHK    8            // t per chunk
#define NSEG    8            // segments for the S scan
#define SEGT    128          // t per segment

#define LOG_EPS (-18.420680743952367f)   // logf(1e-8f)

// ---------------- device scratch (no allocations allowed) ----------------
__device__ float g_Wt[INDIM*NOUT];     // transposed+concatenated weights [k][n]
__device__ float g_bias[NOUT];
__device__ float g_v [M_TOT*64];       // v   (index m*64+d, m = t*8+b)
__device__ float g_k [M_TOT*64];       // k
__device__ float g_la[M_TOT*64];       // log(max(sigmoid(a),eps))
__device__ float g_kd[M_TOT*64];       // k * decay
__device__ float g_csum[NCH*512];      // per-chunk log sums
__device__ float g_P[(NSEG-1)*B_DIM*64*64];  // segment partial outer sums

// ---------------- K0: pack weights (transpose to [k][n]) + bias ----------------
__global__ void pack_weights(const float* __restrict__ Wv, const float* __restrict__ bv,
                             const float* __restrict__ Wk, const float* __restrict__ bk,
                             const float* __restrict__ Wa, const float* __restrict__ ba){
    int idx = blockIdx.x*256 + threadIdx.x;
    if (idx < NOUT*INDIM){
        int j = idx / INDIM;          // output col 0..191
        int k = idx - j*INDIM;        // k 0..511 (coalesced read)
        const float* W = (j < 64) ? Wv : ((j < 128) ? Wk : Wa);
        g_Wt[k*NOUT + j] = W[(j & 63)*INDIM + k];
    }
    if (idx < NOUT){
        g_bias[idx] = (idx < 64) ? bv[idx] : ((idx < 128) ? bk[idx-64] : ba[idx-128]);
    }
}

// ---------------- K1: projection GEMM (8192 x 512) x (512 x 192) ----------------
// Block: 256 threads; tile 64 rows x 192 cols. Thread: 4 rows x 12 cols, plain fmaf.
__global__ void __launch_bounds__(256) proj_kernel(const float* __restrict__ x){
    __shared__ float sW[16*192];   // 12 KB  (k-tile x all 192 n)
    __shared__ float sX[16*64];    // 4 KB   (k-tile x 64 m, transposed)
    __shared__ float sB[192];

    int tid = threadIdx.x;
    int tx = tid & 15;             // n-group: 12 cols
    int ty = tid >> 4;             // m-group: 4 rows (0..15)
    if (tid < 192) sB[tid] = g_bias[tid];
    int mb = blockIdx.x * 64;

    float acc[4][12];
    #pragma unroll
    for (int i = 0; i < 4; i++)
        #pragma unroll
        for (int j = 0; j < 12; j++) acc[i][j] = 0.0f;

    for (int kk = 0; kk < INDIM; kk += 16){
        // W tile: 16*192 = 3072 floats = 768 float4 (3 per thread)
        {
            const float4* src = (const float4*)&g_Wt[kk*NOUT];
            float4* dst = (float4*)sW;
            dst[tid]       = src[tid];
            dst[tid + 256] = src[tid + 256];
            dst[tid + 512] = src[tid + 512];
        }
        // X tile, transposed: sX[k][m]; m = tid>>2 (0..63), kq = tid&3
        {
            int m  = tid >> 2;
            int kq = tid & 3;
            float4 xv = *(const float4*)&x[(mb + m)*INDIM + kk + kq*4];
            sX[(kq*4+0)*64 + m] = xv.x;
            sX[(kq*4+1)*64 + m] = xv.y;
            sX[(kq*4+2)*64 + m] = xv.z;
            sX[(kq*4+3)*64 + m] = xv.w;
        }
        __syncthreads();
        #pragma unroll
        for (int k = 0; k < 16; k++){
            float4 xr = *(float4*)&sX[k*64 + ty*4];
            float xm[4] = {xr.x, xr.y, xr.z, xr.w};
            float4 w0 = *(float4*)&sW[k*192 + tx*12 + 0];
            float4 w1 = *(float4*)&sW[k*192 + tx*12 + 4];
            float4 w2 = *(float4*)&sW[k*192 + tx*12 + 8];
            float wv[12] = {w0.x,w0.y,w0.z,w0.w, w1.x,w1.y,w1.z,w1.w, w2.x,w2.y,w2.z,w2.w};
            #pragma unroll
            for (int mi = 0; mi < 4; mi++)
                #pragma unroll
                for (int nj = 0; nj < 12; nj++)
                    acc[mi][nj] = fmaf(xm[mi], wv[nj], acc[mi][nj]);
        }
        __syncthreads();
    }

    // epilogue: bias + routing (v / k / fp32 stable log-sigmoid)
    #pragma unroll
    for (int mi = 0; mi < 4; mi++){
        int m = mb + ty*4 + mi;      // = t*8 + b
        #pragma unroll
        for (int nj = 0; nj < 12; nj++){
            int n = tx*12 + nj;
            float val = acc[mi][nj] + sB[n];
            if (n < 64){
                g_v[m*64 + n] = val;
            } else if (n < 128){
                g_k[m*64 + (n - 64)] = val;
            } else {
                // log(sigmoid(val)) = min(val,0) - log1p(exp(-|val|)), clamped at log(1e-8)
                float lsig = fminf(val, 0.0f) - log1pf(expf(-fabsf(val)));
                g_la[m*64 + (n - 128)] = fmaxf(lsig, LOG_EPS);
            }
        }
    }
}

// ---------------- K2a: per-chunk log sums ----------------
__global__ void __launch_bounds__(512) chunk_logsum(){
    int c  = blockIdx.x;           // chunk 0..127
    int bn = threadIdx.x;          // (b*64+n) 0..511
    const float* p = g_la + c*TCHK*512 + bn;
    float s = 0.0f;
    #pragma unroll
    for (int i = 0; i < TCHK; i++) s += p[i*512];
    g_csum[c*512 + bn] = s;
}

// ---------------- K2b: decay + fold into k ----------------
__global__ void __launch_bounds__(512) decay_fold(){
    int c  = blockIdx.x;           // chunk 0..127
    int bn = threadIdx.x;
    float carry = 0.0f, total = 0.0f;
    #pragma unroll 8
    for (int j = 0; j < NCH; j++){
        float cs = g_csum[j*512 + bn];
        if (j < c) carry += cs;
        total += cs;
    }
    float denom = expf(total) + 1e-8f;   // matches ref: fp32 cumprod[-1] underflows -> 1e-8
    float inv = 1.0f / denom;
    float cum = carry;
    const float* lap = g_la + c*TCHK*512 + bn;
    const float* kp  = g_k  + c*TCHK*512 + bn;
    float*       kdp = g_kd + c*TCHK*512 + bn;
    #pragma unroll
    for (int i = 0; i < TCHK; i++){
        cum += lap[i*512];
        float dec = expf(cum) * inv;
        kdp[i*512] = kp[i*512] * dec;
    }
}

// ---------------- K4: segment partial outer sums ----------------
// grid (16 dq, 8 b, NSEG-1 seg), block 64 = (dg 0..3) x (nq 0..15)
__global__ void __launch_bounds__(64) seg_partial(){
    int dq = blockIdx.x, b = blockIdx.y, seg = blockIdx.z;
    __shared__ float s_v[SEGT*4];
    int tid = threadIdx.x;
    for (int i = tid; i < SEGT; i += 64){
        float4 vv = *(const float4*)&g_v[(seg*SEGT + i)*512 + b*64 + dq*4];
        *(float4*)&s_v[i*4] = vv;
    }
    __syncthreads();
    int dg = tid >> 4, nq = tid & 15;
    int d = dq*4 + dg;
    float4 acc = make_float4(0.f, 0.f, 0.f, 0.f);
    const float* kdp = g_kd + seg*SEGT*512 + b*64 + nq*4;
    #pragma unroll 8
    for (int t = 0; t < SEGT; t++){
        float4 kd = *(const float4*)(kdp + t*512);
        float vv = s_v[t*4 + dg];
        acc.x = fmaf(vv, kd.x, acc.x);
        acc.y = fmaf(vv, kd.y, acc.y);
        acc.z = fmaf(vv, kd.z, acc.z);
        acc.w = fmaf(vv, kd.w, acc.w);
    }
    *(float4*)&g_P[(seg*B_DIM + b)*4096 + d*64 + nq*4] = acc;
}

// ---------------- K5: segmented scan + store (128 MB) ----------------
// grid (16 dq, 8 b, NSEG seg), block 64 = (dg 0..3) x (nq 0..15)
__global__ void __launch_bounds__(64) scan_kernel(float* __restrict__ out){
    int dq = blockIdx.x, b = blockIdx.y, seg = blockIdx.z;
    __shared__ float s_v[SEGT*4];
    int tid = threadIdx.x;
    for (int i = tid; i < SEGT; i += 64){
        float4 vv = *(const float4*)&g_v[(seg*SEGT + i)*512 + b*64 + dq*4];
        *(float4*)&s_v[i*4] = vv;
    }
    __syncthreads();
    int dg = tid >> 4, nq = tid & 15;
    int d = dq*4 + dg;
    float4 acc = make_float4(0.f, 0.f, 0.f, 0.f);
    for (int s = 0; s < seg; s++){
        float4 pv = *(const float4*)&g_P[(s*B_DIM + b)*4096 + d*64 + nq*4];
        acc.x += pv.x; acc.y += pv.y; acc.z += pv.z; acc.w += pv.w;
    }
    const float* kdp = g_kd + seg*SEGT*512 + b*64 + nq*4;
    float* outp = out + (size_t)(seg*SEGT)*32768 + b*4096 + d*64 + nq*4;
    #pragma unroll 8
    for (int t = 0; t < SEGT; t++){
        float4 kd = *(const float4*)(kdp + t*512);
        float vv = s_v[t*4 + dg];
        acc.x = fmaf(vv, kd.x, acc.x);
        acc.y = fmaf(vv, kd.y, acc.y);
        acc.z = fmaf(vv, kd.z, acc.z);
        acc.w = fmaf(vv, kd.w, acc.w);
        *(float4*)(outp + (size_t)t*32768) = acc;
    }
}

// ---------------- launch ----------------
extern "C" void kernel_launch(void* const* d_in, const int* in_sizes, int n_in,
                              void* d_out, int out_size){
    const float* x  = (const float*)d_in[0];
    const float* Wv = (const float*)d_in[1];
    const float* bv = (const float*)d_in[2];
    const float* Wk = (const float*)d_in[3];
    const float* bk = (const float*)d_in[4];
    const float* Wa = (const float*)d_in[5];
    const float* ba = (const float*)d_in[6];
    float* out = (float*)d_out;

    pack_weights<<<(NOUT*INDIM + 255)/256, 256>>>(Wv, bv, Wk, bk, Wa, ba);
    proj_kernel<<<M_TOT/64, 256>>>(x);
    chunk_logsum<<<NCH, 512>>>();
    decay_fold<<<NCH, 512>>>();
    dim3 g4(16, B_DIM, NSEG-1);
    seg_partial<<<g4, 64>>>();
    dim3 g5(16, B_DIM, NSEG);
    scan_kernel<<<g5, 64>>>(out);
}